// round 8
// baseline (speedup 1.0000x reference)
#include <cuda_runtime.h>
#include <math.h>

#define BB   32
#define TT   400
#define MELD 80
#define LLd  256
#define UU   512
#define MMa  200
#define U4   2048
#define U3   1536
#define BT   (BB*TT)      // 12800
#define NBLK 148
#define GBLK 128
#define NTHR 1024
#define HN   (UU*BB)      // 16384

// ---------------- scratch ----------------
__device__ __align__(16) float g_inT [BT*MELD];
__device__ __align__(16) float g_h1  [BT*UU];
__device__ __align__(16) float g_xp  [BT*LLd];
__device__ __align__(16) float g_keys[BB*MMa*UU];
__device__ __align__(16) float g_xpart[(size_t)BT*U4];
__device__ __align__(16) float g_x   [BT*UU];
__device__ __align__(16) float g_y1  [BT*UU];
__device__ __align__(16) float g_xsum[BT*UU];
__device__ __align__(16) float g_xz  [(size_t)BT*U3];
__device__ __align__(16) float g_hT  [2*HN];         // DOUBLE-BUFFERED h, [buf][u][b]
__device__ __align__(16) float g_q   [BB*UU];        // q, [b][u]
__device__ __align__(16) float g_rec [U4*BB];        // rec, [col][b]
__device__ __align__(16) float g_actxT[2*LLd*BB];    // partial ctx, [half][k][b]
__device__ __align__(16) float g_stats[BB*4];        // [b][half][mx,sum]
// sync flags — each flag padded to its own 128B line (32 ints)
__device__ int g_fq  [32*32];
__device__ int g_frec[128*32];
__device__ int g_fctx[64*32];
__device__ int g_fh  [148*32];
__device__ int g_fgru[128*32];
__device__ unsigned g_cnt = 0;
__device__ unsigned g_gen = 0;

__device__ __forceinline__ unsigned ld_acq_u(const unsigned* p) {
    unsigned v;
    asm volatile("ld.acquire.gpu.u32 %0, [%1];" : "=r"(v) : "l"(p));
    return v;
}
__device__ __forceinline__ int ld_flag(const int* p) {
    int v;
    asm volatile("ld.global.acquire.gpu.b32 %0, [%1];" : "=r"(v) : "l"(p));
    return v;
}

// one-shot barrier for init
__device__ __forceinline__ void grid_barrier0(unsigned nb)
{
    __syncthreads();
    if (threadIdx.x == 0) {
        __threadfence();
        unsigned my   = ld_acq_u(&g_gen);
        unsigned prev = atomicAdd(&g_cnt, 1u);
        if (prev == nb - 1u) {
            atomicExch(&g_cnt, 0u);
            __threadfence();
            atomicAdd(&g_gen, 1u);
        } else {
            while (ld_acq_u(&g_gen) == my) { __nanosleep(32); }
        }
        __threadfence();
    }
    __syncthreads();
}

// wait until all `count` padded flags >= target
__device__ __forceinline__ void wait_flags(const int* flags, int count, int target)
{
    if (threadIdx.x < 32) {
        bool ok;
        int spins = 0;
        do {
            ok = true;
            for (int i = threadIdx.x; i < count; i += 32)
                ok &= (ld_flag(flags + i * 32) >= target);
            if (!ok && ++spins > 2) __nanosleep(128);
        } while (!__all_sync(0xffffffffu, ok));
    }
    __syncthreads();
}

__device__ __forceinline__ void arrive(int* flag, int v)
{
    __syncthreads();
    if (threadIdx.x == 0) {
        __threadfence();
        asm volatile("st.release.gpu.b32 [%0], %1;" :: "l"(flag), "r"(v) : "memory");
    }
}

__device__ __forceinline__ float sig(float x) { return 1.f / (1.f + __expf(-x)); }
__device__ __forceinline__ float tanh_ap(float x) {
    float y; asm("tanh.approx.f32 %0, %1;" : "=f"(y) : "f"(x)); return y;
}

// ---------------- repack inputs [B,T,80] -> [T,B,80] ----------------
__global__ void repack_inputs(const float* __restrict__ in)
{
    int i = blockIdx.x * blockDim.x + threadIdx.x;
    if (i < BT * MELD) {
        int d = i % MELD;
        int r = i / MELD;
        int t = r >> 5, b = r & 31;
        g_inT[i] = in[((size_t)b * TT + t) * MELD + d];
    }
}

__global__ void add_kernel()
{
    int i = blockIdx.x * blockDim.x + threadIdx.x;
    if (i < BT * UU) g_xsum[i] = g_x[i] + g_y1[i];
}

// ---------------- 128x128x16 fp32 GEMM, 8x8 per thread ----------------
__global__ void __launch_bounds__(256) gemm128(
    const float* __restrict__ A, const float* __restrict__ W,
    const float* __restrict__ bias, float* __restrict__ C,
    int N, int K, int doRelu, int remapTB)
{
    __shared__ float Asf[16*132];
    __shared__ float Bsf[16*128];
    const int tid = threadIdx.x;
    const int m0 = blockIdx.y * 128, n0 = blockIdx.x * 128;
    const int tx = tid & 15, ty = tid >> 4;
    const int ar = tid >> 2, ak = (tid & 3) * 4;
    const int br = tid >> 5, bn = (tid & 31) * 4;
    float acc[8][8] = {};

    for (int k0 = 0; k0 < K; k0 += 16) {
#pragma unroll
        for (int h = 0; h < 2; h++) {
            int row = ar + 64*h;
            float4 a4 = *(const float4*)&A[(size_t)(m0 + row) * K + k0 + ak];
            Asf[(ak+0)*132 + row] = a4.x; Asf[(ak+1)*132 + row] = a4.y;
            Asf[(ak+2)*132 + row] = a4.z; Asf[(ak+3)*132 + row] = a4.w;
        }
#pragma unroll
        for (int h = 0; h < 2; h++) {
            int gn = n0 + bn;
            float4 b4 = make_float4(0.f,0.f,0.f,0.f);
            if (gn < N) b4 = *(const float4*)&W[(size_t)(k0 + br + 8*h) * N + gn];
            *(float4*)&Bsf[(br+8*h)*128 + bn] = b4;
        }
        __syncthreads();
#pragma unroll
        for (int kk = 0; kk < 16; kk++) {
            float a[8], bv[8];
            *(float4*)&a[0]  = *(const float4*)&Asf[kk*132 + ty*8];
            *(float4*)&a[4]  = *(const float4*)&Asf[kk*132 + ty*8 + 4];
            *(float4*)&bv[0] = *(const float4*)&Bsf[kk*128 + tx*8];
            *(float4*)&bv[4] = *(const float4*)&Bsf[kk*128 + tx*8 + 4];
#pragma unroll
            for (int i = 0; i < 8; i++)
#pragma unroll
                for (int j = 0; j < 8; j++) acc[i][j] += a[i] * bv[j];
        }
        __syncthreads();
    }
#pragma unroll
    for (int i = 0; i < 8; i++) {
        int row = m0 + ty*8 + i;
#pragma unroll
        for (int h = 0; h < 2; h++) {
            int col = n0 + tx*8 + h*4;
            if (col >= N) continue;
            float4 v;
            v.x = acc[i][h*4+0]; v.y = acc[i][h*4+1];
            v.z = acc[i][h*4+2]; v.w = acc[i][h*4+3];
            if (bias) {
                float4 bb = *(const float4*)&bias[col];
                v.x += bb.x; v.y += bb.y; v.z += bb.z; v.w += bb.w;
            }
            if (doRelu) {
                v.x = fmaxf(v.x, 0.f); v.y = fmaxf(v.y, 0.f);
                v.z = fmaxf(v.z, 0.f); v.w = fmaxf(v.w, 0.f);
            }
            size_t oi;
            if (remapTB) { int t = row >> 5, b = row & 31; oi = ((size_t)b * TT + t) * N + col; }
            else         { oi = (size_t)row * N + col; }
            *(float4*)&C[oi] = v;
        }
    }
}

// ============================================================
// persistent attention-LSTM, dataflow-synced, padded flags
//   A: all 148 stage hT; rec units on blocks 0..127 (16 cols),
//      q units on blocks 116..147 (16 cols; q first on 116..127)
//   B: blocks 0..63: attention (b, half)
//   C: blocks 0..127: ctx combine + ctx@K2 (16 cols) + gates (4 cells, all b)
// ============================================================
#define SMF_L 20480
__global__ void __launch_bounds__(NTHR, 1) lstm_attn(
    const float* __restrict__ attended,
    const float* __restrict__ qW, const float* __restrict__ qb,
    const float* __restrict__ vW, const float* __restrict__ vb,
    const float* __restrict__ lstmK, const float* __restrict__ lstmR)
{
    extern __shared__ float sm[];
    const int tid = threadIdx.x, bid = blockIdx.x;
    const int lane = tid & 31, wid = tid >> 5;

    // phase-A aliases
    float* hT = sm;              // [512][32]
    float* pA = sm + 16384;      // [8][16][32]
    // phase-B aliases
    float* q_s  = sm;            // 512
    float* v_s  = sm + 512;      // 512
    float* sc   = sm + 1024;     // 128
    float* ctxp = sm + 1152;     // 1024
    // phase-C aliases
    float* a1s  = sm;            // 32
    float* a2s  = sm + 32;       // 32
    float* ctxT = sm + 64;       // [256][32]
    float* pC   = sm + 64 + 8192;  // [8][16][32] = 4096
    float* zsm  = sm + 64 + 12288; // 512

    // init: reset flags, zero both h buffers
    if (tid == 0) {
        if (bid >= 116) g_fq[(bid-116)*32] = 0;
        if (bid < 128)  g_frec[bid*32] = 0;
        if (bid < 64)   g_fctx[bid*32] = 0;
        g_fh[bid*32] = 0;
    }
    for (int i = bid*NTHR + tid; i < 2*HN; i += NBLK*NTHR) g_hT[i] = 0.f;
    float creg = 0.f;
    float vb0 = 0.f;
    if (bid < 64) vb0 = __ldg(vb);
    grid_barrier0(NBLK);

    const float4* R4  = (const float4*)lstmR;               // [512][512 f4]
    const float4* qW4 = (const float4*)qW;                  // [512][128 f4]
    const float4* K24 = (const float4*)(lstmK + (size_t)LLd * U4); // rows 256..511

    for (int t = 0; t < TT; ++t) {
        // ---------- phase A ----------
        wait_flags(g_fh, 148, t);
        {
            const float4* hbuf = (const float4*)(g_hT + ((t+1)&1)*HN);
            for (int i = tid; i < 4096; i += NTHR)
                ((float4*)hT)[i] = __ldcg(hbuf + i);
        }
        __syncthreads();

        // q pass (blocks 116..147)
        if (bid >= 116) {
            const int qu = bid - 116;
            const int c0 = qu * 16;
            {
                const int b = tid & 31, cq = (tid >> 5) & 3, ks = tid >> 7;
                const float4* wp = qW4 + (size_t)(ks * 64) * 128 + (c0 >> 2) + cq;
                const float* hp = hT + (ks * 64) * 32 + b;
                float4 acc = make_float4(0.f,0.f,0.f,0.f);
#pragma unroll 8
                for (int k = 0; k < 64; ++k) {
                    float hv = hp[k * 32];
                    float4 w = __ldg(wp); wp += 128;
                    acc.x += hv*w.x; acc.y += hv*w.y; acc.z += hv*w.z; acc.w += hv*w.w;
                }
                float* pd = pA + ks*512 + (cq*4)*32 + b;
                pd[0] = acc.x; pd[32] = acc.y; pd[64] = acc.z; pd[96] = acc.w;
            }
            __syncthreads();
            if (tid < 512) {
                const int c = tid >> 5, b = tid & 31;
                float s = __ldg(qb + c0 + c);
#pragma unroll
                for (int j = 0; j < 8; ++j) s += pA[j*512 + c*32 + b];
                g_q[b*UU + c0 + c] = s;
            }
            arrive(&g_fq[qu*32], t + 1);
        }

        // rec pass (blocks 0..127)
        if (bid < 128) {
            const int c0 = bid * 16;
            {
                const int b = tid & 31, cq = (tid >> 5) & 3, ks = tid >> 7;
                const float4* wp = R4 + (size_t)(ks * 64) * 512 + (c0 >> 2) + cq;
                const float* hp = hT + (ks * 64) * 32 + b;
                float4 acc = make_float4(0.f,0.f,0.f,0.f);
#pragma unroll 8
                for (int k = 0; k < 64; ++k) {
                    float hv = hp[k * 32];
                    float4 w = __ldg(wp); wp += 512;
                    acc.x += hv*w.x; acc.y += hv*w.y; acc.z += hv*w.z; acc.w += hv*w.w;
                }
                float* pd = pA + ks*512 + (cq*4)*32 + b;
                pd[0] = acc.x; pd[32] = acc.y; pd[64] = acc.z; pd[96] = acc.w;
            }
            __syncthreads();
            if (tid < 512) {
                const int c = tid >> 5, b = tid & 31;
                float s = __ldcg(&g_xpart[((size_t)t*BB + b)*U4 + c0 + c]);
#pragma unroll
                for (int j = 0; j < 8; ++j) s += pA[j*512 + c*32 + b];
                g_rec[(c0 + c)*32 + b] = s;
            }
            arrive(&g_frec[bid*32], t + 1);
        }

        // ---------- phase B: attention (blocks 0..63) ----------
        if (bid < 64) {
            const int b = bid >> 1, half = bid & 1, m0h = half * 100;
            wait_flags(g_fq, 32, t + 1);
            if (tid < UU) { q_s[tid] = __ldcg(&g_q[b*UU + tid]); v_s[tid] = __ldg(vW + tid); }
            __syncthreads();
            for (int m = wid; m < 100; m += 32) {
                const float* krow = g_keys + ((size_t)(b*MMa + m0h + m)) * UU;
                float acc = 0.f;
#pragma unroll
                for (int j = 0; j < 16; ++j) {
                    int uu = lane + 32*j;
                    acc += v_s[uu] * tanh_ap(__ldg(krow + uu) + q_s[uu]);
                }
#pragma unroll
                for (int o = 16; o > 0; o >>= 1) acc += __shfl_down_sync(0xffffffffu, acc, o);
                if (lane == 0) sc[m] = acc + vb0;
            }
            __syncthreads();
            // single-warp softmax stats over 100 scores
            if (tid < 32) {
                float v[4];
#pragma unroll
                for (int j = 0; j < 4; ++j) {
                    int m = tid + 32*j;
                    v[j] = (m < 100) ? sc[m] : -1e30f;
                }
                float mx = fmaxf(fmaxf(v[0], v[1]), fmaxf(v[2], v[3]));
#pragma unroll
                for (int o = 16; o > 0; o >>= 1) mx = fmaxf(mx, __shfl_xor_sync(0xffffffffu, mx, o));
                float ssum = 0.f;
#pragma unroll
                for (int j = 0; j < 4; ++j) {
                    int m = tid + 32*j;
                    float e = (m < 100) ? __expf(v[j] - mx) : 0.f;
                    if (m < 128) sc[m] = e;
                    ssum += e;
                }
#pragma unroll
                for (int o = 16; o > 0; o >>= 1) ssum += __shfl_xor_sync(0xffffffffu, ssum, o);
                if (tid == 0) { g_stats[b*4 + half*2] = mx; g_stats[b*4 + half*2 + 1] = ssum; }
            }
            __syncthreads();
            {
                const int d = tid & 255, mp = tid >> 8;
                const float* att = attended + ((size_t)(b*MMa + m0h + mp*25)) * LLd + d;
                float acc = 0.f;
#pragma unroll
                for (int m = 0; m < 25; ++m) acc += sc[mp*25 + m] * __ldg(att + (size_t)m * LLd);
                ctxp[mp*256 + d] = acc;
            }
            __syncthreads();
            if (tid < 256)
                g_actxT[half*8192 + tid*32 + b] =
                    ctxp[tid] + ctxp[256+tid] + ctxp[512+tid] + ctxp[768+tid];
            arrive(&g_fctx[bid*32], t + 1);
        }

        // ---------- phase C: gates (blocks 0..127, 4 cells each) ----------
        if (bid < 128) {
            const int u0 = bid * 4;
            wait_flags(g_fctx, 64, t + 1);
            if (tid < 32) {
                float m1 = __ldcg(&g_stats[tid*4 + 0]), s1 = __ldcg(&g_stats[tid*4 + 1]);
                float m2 = __ldcg(&g_stats[tid*4 + 2]), s2 = __ldcg(&g_stats[tid*4 + 3]);
                float mxa = fmaxf(m1, m2);
                float w1 = __expf(m1 - mxa), w2 = __expf(m2 - mxa);
                float inv = 1.f / (w1*s1 + w2*s2);
                a1s[tid] = w1 * inv; a2s[tid] = w2 * inv;
            }
            __syncthreads();
            for (int i = tid; i < 8192; i += NTHR) {
                int b2 = i & 31;
                ctxT[i] = a1s[b2]*__ldcg(&g_actxT[i]) + a2s[b2]*__ldcg(&g_actxT[8192 + i]);
            }
            wait_flags(g_frec, 128, t + 1);   // includes __syncthreads (covers ctxT)
            {
                const int b2 = tid & 31, g = (tid >> 5) & 3, ks = tid >> 7;
                const float4* wp = K24 + (size_t)(ks*32)*512 + ((g*UU + u0) >> 2);
                const float* cp = ctxT + (ks*32)*32 + b2;
                float4 acc = make_float4(0.f,0.f,0.f,0.f);
#pragma unroll 8
                for (int k = 0; k < 32; ++k) {
                    float cv = cp[k*32];
                    float4 w = __ldg(wp); wp += 512;
                    acc.x += cv*w.x; acc.y += cv*w.y; acc.z += cv*w.z; acc.w += cv*w.w;
                }
                float* pd = pC + ks*512 + (g*4)*32 + b2;
                pd[0] = acc.x; pd[32] = acc.y; pd[64] = acc.z; pd[96] = acc.w;
            }
            __syncthreads();
            if (tid < 512) {
                const int c16 = tid >> 5, b2 = tid & 31;   // c16 = g*4 + j
                float s = 0.f;
#pragma unroll
                for (int j = 0; j < 8; ++j) s += pC[j*512 + c16*32 + b2];
                const int g = c16 >> 2, jj = c16 & 3;
                s += __ldcg(&g_rec[(g*UU + u0 + jj)*32 + b2]);
                zsm[c16*32 + b2] = s;
            }
            __syncthreads();
            if (tid < 128) {
                const int uu = tid >> 5, b2 = tid & 31;
                float ig = sig(zsm[(0  + uu)*32 + b2]);
                float fg = sig(zsm[(4  + uu)*32 + b2]);
                float gg = tanhf(zsm[(8  + uu)*32 + b2]);
                float og = sig(zsm[(12 + uu)*32 + b2]);
                float cn = fg * creg + ig * gg;
                creg = cn;
                float hn = og * tanhf(cn);
                g_hT[(t&1)*HN + (u0 + uu)*32 + b2] = hn;
                g_x[((size_t)t*BB + b2)*UU + u0 + uu] = hn;
            }
        }
        arrive(&g_fh[bid*32], t + 1);
    }
}

// ============================================================
// persistent GRU: 128 blocks × 4 cells, double-buffered h, 1 sync/step
// ============================================================
#define SMF_G 19840
__global__ void __launch_bounds__(NTHR, 1) gru_seq(
    const float* __restrict__ R, const float* __restrict__ br,
    const float* __restrict__ xz, float* __restrict__ yout, int accumulate)
{
    extern __shared__ float sm[];
    float* hT  = sm;                 // [512][32]
    float* pG  = sm + 16384;         // [8][12][32]
    float* rrs = sm + 16384 + 3072;  // [384]
    const int tid = threadIdx.x, bid = blockIdx.x;
    const int u0 = bid * 4;

    if (tid == 0) g_fgru[bid*32] = 0;
    for (int i = bid*NTHR + tid; i < 2*HN; i += GBLK*NTHR) g_hT[i] = 0.f;
    grid_barrier0(GBLK);

    const float4* R4 = (const float4*)R;   // [512][384 f4]

    for (int t = 0; t < TT; ++t) {
        wait_flags(g_fgru, GBLK, t);
        {
            const float4* hbuf = (const float4*)(g_hT + ((t+1)&1)*HN);
            for (int i = tid; i < 4096; i += NTHR)
                ((float4*)hT)[i] = __ldcg(hbuf + i);
        }
        __syncthreads();

        if (tid < 768) {
            const int b = tid & 31, rest = tid >> 5;     // 24 = 3g x 8ks
            const int g = rest >> 3, ks = rest & 7;
            const float4* wp = R4 + (size_t)(ks*64)*384 + ((g*UU + u0) >> 2);
            const float* hp = hT + (ks*64)*32 + b;
            float4 acc = make_float4(0.f,0.f,0.f,0.f);
#pragma unroll 8
            for (int k = 0; k < 64; ++k) {
                float hv = hp[k*32];
                float4 w = __ldg(wp); wp += 384;
                acc.x += hv*w.x; acc.y += hv*w.y; acc.z += hv*w.z; acc.w += hv*w.w;
            }
            float* pd = pG + ks*384 + (g*4)*32 + b;
            pd[0] = acc.x; pd[32] = acc.y; pd[64] = acc.z; pd[96] = acc.w;
        }
        __syncthreads();
        if (tid < 384) {
            const int g = tid >> 7, uu = (tid >> 5) & 3, b = tid & 31;
            float s = 0.f;
#pragma unroll
            for (int j = 0; j < 8; ++j) s += pG[j*384 + (g*4 + uu)*32 + b];
            rrs[tid] = s + __ldg(br + g*UU + u0 + uu);
        }
        __syncthreads();
        if (tid < 128) {
            const int uu = tid >> 5, b = tid & 31;
            const int ug = u0 + uu;
            const float* xzr = xz + ((size_t)t*BB + b) * U3;
            float z = sig(__ldg(xzr + ug)           + rrs[uu*32 + b]);
            float r = sig(__ldg(xzr + UU + ug)      + rrs[128 + uu*32 + b]);
            float hh = tanhf(__ldg(xzr + 2*UU + ug) + r * rrs[256 + uu*32 + b]);
            float hold = hT[ug*32 + b];
            float hn = z * hold + (1.f - z) * hh;
            g_hT[(t&1)*HN + ug*32 + b] = hn;
            size_t oi = ((size_t)t*BB + b)*UU + ug;
            if (accumulate) yout[oi] += hn; else yout[oi] = hn;
        }
        arrive(&g_fgru[bid*32], t + 1);
    }
}

// ---------------- launch ----------------
extern "C" void kernel_launch(void* const* d_in, const int* in_sizes, int n_in,
                              void* d_out, int out_size)
{
    const float* inputs   = (const float*)d_in[0];
    const float* attended = (const float*)d_in[1];
    const float* pre_W1   = (const float*)d_in[2];
    const float* pre_b1   = (const float*)d_in[3];
    const float* pre_W2   = (const float*)d_in[4];
    const float* pre_b2   = (const float*)d_in[5];
    const float* key_W    = (const float*)d_in[6];
    const float* key_b    = (const float*)d_in[7];
    const float* query_W  = (const float*)d_in[8];
    const float* query_b  = (const float*)d_in[9];
    const float* attnv_W  = (const float*)d_in[10];
    const float* attnv_b  = (const float*)d_in[11];
    const float* lstm_K   = (const float*)d_in[12];
    const float* lstm_R   = (const float*)d_in[13];
    const float* lstm_b   = (const float*)d_in[14];
    const float* gru1_K   = (const float*)d_in[15];
    const float* gru1_R   = (const float*)d_in[16];
    const float* gru1_b   = (const float*)d_in[17];
    const float* gru2_K   = (const float*)d_in[18];
    const float* gru2_R   = (const float*)d_in[19];
    const float* gru2_b   = (const float*)d_in[20];
    const float* proj_W   = (const float*)d_in[21];
    float* out = (float*)d_out;

    float *inT, *h1, *xp, *keys, *xpart, *x, *y1, *xsum, *xz;
    cudaGetSymbolAddress((void**)&inT,   g_inT);
    cudaGetSymbolAddress((void**)&h1,    g_h1);
    cudaGetSymbolAddress((void**)&xp,    g_xp);
    cudaGetSymbolAddress((void**)&keys,  g_keys);
    cudaGetSymbolAddress((void**)&xpart, g_xpart);
    cudaGetSymbolAddress((void**)&x,     g_x);
    cudaGetSymbolAddress((void**)&y1,    g_y1);
    cudaGetSymbolAddress((void**)&xsum,  g_xsum);
    cudaGetSymbolAddress((void**)&xz,    g_xz);

    cudaFuncSetAttribute(lstm_attn, cudaFuncAttributeMaxDynamicSharedMemorySize,
                         SMF_L * (int)sizeof(float));
    cudaFuncSetAttribute(gru_seq, cudaFuncAttributeMaxDynamicSharedMemorySize,
                         SMF_G * (int)sizeof(float));

    // 1) repack inputs to [T,B,80]
    repack_inputs<<<(BT*MELD + 255)/256, 256>>>(inputs);
    // 2) prenet
    gemm128<<<dim3(4, 100), 256>>>(inT, pre_W1, pre_b1, h1, UU,  MELD, 1, 0);
    gemm128<<<dim3(2, 100), 256>>>(h1,  pre_W2, pre_b2, xp, LLd, UU,   1, 0);
    // 3) keys
    gemm128<<<dim3(4, 50),  256>>>(attended, key_W, key_b, keys, UU, LLd, 0, 0);
    // 4) LSTM input part: xp @ lstm_K[:256] + lstm_b
    gemm128<<<dim3(16, 100), 256>>>(xp, lstm_K, lstm_b, xpart, U4, LLd, 0, 0);
    // 5) attention LSTM (persistent, dataflow-synced)
    lstm_attn<<<NBLK, NTHR, SMF_L*sizeof(float)>>>(
        attended, query_W, query_b, attnv_W, attnv_b, lstm_K, lstm_R);
    // 6) GRU1
    gemm128<<<dim3(12, 100), 256>>>(x, gru1_K, gru1_b, xz, U3, UU, 0, 0);
    gru_seq<<<GBLK, NTHR, SMF_G*sizeof(float)>>>(gru1_R, gru1_b + U3, xz, y1, 0);
    // 7) xsum = x + y1
    add_kernel<<<(BT*UU + 255)/256, 256>>>();
    // 8) GRU2 on xsum, accumulate y2 into xsum
    gemm128<<<dim3(12, 100), 256>>>(xsum, gru2_K, gru2_b, xz, U3, UU, 0, 0);
    gru_seq<<<GBLK, NTHR, SMF_G*sizeof(float)>>>(gru2_R, gru2_b + U3, xz, xsum, 1);
    // 9) mel = relu(xsum @ proj_W) remapped to [B,T,80]
    gemm128<<<dim3(1, 100), 256>>>(xsum, proj_W, nullptr, out, MELD, UU, 1, 1);
}

// round 9
// speedup vs baseline: 1.0226x; 1.0226x over previous
#include <cuda_runtime.h>
#include <math.h>

#define BB   32
#define TT   400
#define MELD 80
#define LLd  256
#define UU   512
#define MMa  200
#define U4   2048
#define U3   1536
#define BT   (BB*TT)      // 12800
#define NBLK 148
#define GBLK 128
#define NTHR 1024
#define HN   (UU*BB)      // 16384
#define CW   2560         // combined [qW | R] width

// ---------------- scratch ----------------
__device__ __align__(16) float g_inT [BT*MELD];
__device__ __align__(16) float g_h1  [BT*UU];
__device__ __align__(16) float g_xp  [BT*LLd];
__device__ __align__(16) float g_keys[BB*MMa*UU];
__device__ __align__(16) float g_xpart[(size_t)BT*U4];
__device__ __align__(16) float g_x   [BT*UU];
__device__ __align__(16) float g_y1  [BT*UU];
__device__ __align__(16) float g_xsum[BT*UU];
__device__ __align__(16) float g_xz  [(size_t)BT*U3];
__device__ __align__(16) float g_Rq  [UU*CW];        // [512][2560] = [qW | lstm_R]
__device__ __align__(16) float g_hT  [2*HN];         // double-buffered h, [buf][u][b]
__device__ __align__(16) float g_q   [BB*UU];        // q, [b][u]
__device__ __align__(16) float g_rec [U4*BB];        // rec, [col][b]
__device__ __align__(16) float g_actxT[2*LLd*BB];    // partial ctx, [half][k][b]
__device__ __align__(16) float g_stats[BB*4];        // [b][half][mx,sum]
// sync flags — each flag padded to its own 128B line
__device__ int g_fq  [32*32];
__device__ int g_frec[128*32];
__device__ int g_fctx[64*32];
__device__ int g_fh  [148*32];
__device__ int g_fgru[128*32];
__device__ unsigned g_cnt = 0;
__device__ unsigned g_gen = 0;

__device__ __forceinline__ unsigned ld_acq_u(const unsigned* p) {
    unsigned v;
    asm volatile("ld.acquire.gpu.u32 %0, [%1];" : "=r"(v) : "l"(p));
    return v;
}
__device__ __forceinline__ int ld_flag(const int* p) {
    int v;
    asm volatile("ld.global.acquire.gpu.b32 %0, [%1];" : "=r"(v) : "l"(p));
    return v;
}

// one-shot barrier for init
__device__ __forceinline__ void grid_barrier0(unsigned nb)
{
    __syncthreads();
    if (threadIdx.x == 0) {
        __threadfence();
        unsigned my   = ld_acq_u(&g_gen);
        unsigned prev = atomicAdd(&g_cnt, 1u);
        if (prev == nb - 1u) {
            atomicExch(&g_cnt, 0u);
            __threadfence();
            atomicAdd(&g_gen, 1u);
        } else {
            while (ld_acq_u(&g_gen) == my) { __nanosleep(32); }
        }
        __threadfence();
    }
    __syncthreads();
}

// wait until all `count` padded flags >= target — PURE SPIN (sleep only as failsafe)
__device__ __forceinline__ void wait_flags(const int* flags, int count, int target)
{
    if (threadIdx.x < 32) {
        bool ok;
        int spins = 0;
        do {
            ok = true;
            for (int i = threadIdx.x; i < count; i += 32)
                ok &= (ld_flag(flags + i * 32) >= target);
            if (!ok && ++spins > 64) __nanosleep(256);
        } while (!__all_sync(0xffffffffu, ok));
    }
    __syncthreads();
}

__device__ __forceinline__ void arrive(int* flag, int v)
{
    __syncthreads();
    if (threadIdx.x == 0) {
        __threadfence();
        asm volatile("st.release.gpu.b32 [%0], %1;" :: "l"(flag), "r"(v) : "memory");
    }
}

__device__ __forceinline__ float sig(float x) { return 1.f / (1.f + __expf(-x)); }
__device__ __forceinline__ float tanh_ap(float x) {
    float y; asm("tanh.approx.f32 %0, %1;" : "=f"(y) : "f"(x)); return y;
}

// ---------------- repack inputs [B,T,80] -> [T,B,80] ----------------
__global__ void repack_inputs(const float* __restrict__ in)
{
    int i = blockIdx.x * blockDim.x + threadIdx.x;
    if (i < BT * MELD) {
        int d = i % MELD;
        int r = i / MELD;
        int t = r >> 5, b = r & 31;
        g_inT[i] = in[((size_t)b * TT + t) * MELD + d];
    }
}

// build combined weight matrix [qW | lstm_R]
__global__ void build_Rq(const float* __restrict__ qW, const float* __restrict__ R)
{
    int i = blockIdx.x * blockDim.x + threadIdx.x;
    if (i < UU * CW) {
        int r = i / CW, c = i % CW;
        g_Rq[i] = (c < UU) ? qW[(size_t)r * UU + c] : R[(size_t)r * U4 + (c - UU)];
    }
}

__global__ void add_kernel()
{
    int i = blockIdx.x * blockDim.x + threadIdx.x;
    if (i < BT * UU) g_xsum[i] = g_x[i] + g_y1[i];
}

// ---------------- 128x128x16 fp32 GEMM, 8x8 per thread ----------------
__global__ void __launch_bounds__(256) gemm128(
    const float* __restrict__ A, const float* __restrict__ W,
    const float* __restrict__ bias, float* __restrict__ C,
    int N, int K, int doRelu, int remapTB)
{
    __shared__ float Asf[16*132];
    __shared__ float Bsf[16*128];
    const int tid = threadIdx.x;
    const int m0 = blockIdx.y * 128, n0 = blockIdx.x * 128;
    const int tx = tid & 15, ty = tid >> 4;
    const int ar = tid >> 2, ak = (tid & 3) * 4;
    const int br = tid >> 5, bn = (tid & 31) * 4;
    float acc[8][8] = {};

    for (int k0 = 0; k0 < K; k0 += 16) {
#pragma unroll
        for (int h = 0; h < 2; h++) {
            int row = ar + 64*h;
            float4 a4 = *(const float4*)&A[(size_t)(m0 + row) * K + k0 + ak];
            Asf[(ak+0)*132 + row] = a4.x; Asf[(ak+1)*132 + row] = a4.y;
            Asf[(ak+2)*132 + row] = a4.z; Asf[(ak+3)*132 + row] = a4.w;
        }
#pragma unroll
        for (int h = 0; h < 2; h++) {
            int gn = n0 + bn;
            float4 b4 = make_float4(0.f,0.f,0.f,0.f);
            if (gn < N) b4 = *(const float4*)&W[(size_t)(k0 + br + 8*h) * N + gn];
            *(float4*)&Bsf[(br+8*h)*128 + bn] = b4;
        }
        __syncthreads();
#pragma unroll
        for (int kk = 0; kk < 16; kk++) {
            float a[8], bv[8];
            *(float4*)&a[0]  = *(const float4*)&Asf[kk*132 + ty*8];
            *(float4*)&a[4]  = *(const float4*)&Asf[kk*132 + ty*8 + 4];
            *(float4*)&bv[0] = *(const float4*)&Bsf[kk*128 + tx*8];
            *(float4*)&bv[4] = *(const float4*)&Bsf[kk*128 + tx*8 + 4];
#pragma unroll
            for (int i = 0; i < 8; i++)
#pragma unroll
                for (int j = 0; j < 8; j++) acc[i][j] += a[i] * bv[j];
        }
        __syncthreads();
    }
#pragma unroll
    for (int i = 0; i < 8; i++) {
        int row = m0 + ty*8 + i;
#pragma unroll
        for (int h = 0; h < 2; h++) {
            int col = n0 + tx*8 + h*4;
            if (col >= N) continue;
            float4 v;
            v.x = acc[i][h*4+0]; v.y = acc[i][h*4+1];
            v.z = acc[i][h*4+2]; v.w = acc[i][h*4+3];
            if (bias) {
                float4 bb = *(const float4*)&bias[col];
                v.x += bb.x; v.y += bb.y; v.z += bb.z; v.w += bb.w;
            }
            if (doRelu) {
                v.x = fmaxf(v.x, 0.f); v.y = fmaxf(v.y, 0.f);
                v.z = fmaxf(v.z, 0.f); v.w = fmaxf(v.w, 0.f);
            }
            size_t oi;
            if (remapTB) { int t = row >> 5, b = row & 31; oi = ((size_t)b * TT + t) * N + col; }
            else         { oi = (size_t)row * N + col; }
            *(float4*)&C[oi] = v;
        }
    }
}

// ============================================================
// persistent attention-LSTM
//  A (blocks 64..147): stage hT; combined-matvec units (160 x 16 cols,
//      units 0..31 = q, 32..159 = rec); q units scheduled first
//  B (blocks 0..63):   attention (b, half) — runs CONCURRENTLY with rec
//  C (blocks 0..127):  ctx combine + ctx@K2 + gates (4 cells, all b)
// ============================================================
#define SMF_L 20480
__global__ void __launch_bounds__(NTHR, 1) lstm_attn(
    const float* __restrict__ attended,
    const float* __restrict__ qb,
    const float* __restrict__ vW, const float* __restrict__ vb,
    const float* __restrict__ lstmK)
{
    extern __shared__ float sm[];
    const int tid = threadIdx.x, bid = blockIdx.x;
    const int lane = tid & 31, wid = tid >> 5;

    // phase-A aliases
    float* hT = sm;              // [512][32]
    float* pA = sm + 16384;      // [8][16][32]
    // phase-B aliases
    float* q_s  = sm;            // 512
    float* v_s  = sm + 512;      // 512
    float* sc   = sm + 1024;     // 128
    float* ctxp = sm + 1152;     // 1024
    // phase-C aliases
    float* a1s  = sm;            // 32
    float* a2s  = sm + 32;       // 32
    float* ctxT = sm + 64;       // [256][32]
    float* pC   = sm + 64 + 8192;  // [8][16][32]
    float* zsm  = sm + 64 + 12288; // 512

    // init flags, zero both h buffers
    if (tid == 0) {
        if (bid >= 64) {
            int j = bid - 64;
            if (j < 32) g_fq[j*32] = 0; else g_frec[(j-32)*32] = 0;
            if (j < 76) g_frec[(52 + j)*32] = 0;   // unit 84+j -> frec[84+j-32]
        }
        if (bid < 64) g_fctx[bid*32] = 0;
        g_fh[bid*32] = 0;
    }
    for (int i = bid*NTHR + tid; i < 2*HN; i += NBLK*NTHR) g_hT[i] = 0.f;
    float creg = 0.f;
    float vb0 = 0.f;
    if (bid < 64) vb0 = __ldg(vb);
    grid_barrier0(NBLK);

    const float4* Rq4 = (const float4*)g_Rq;                // [512][640 f4]
    const float4* K24 = (const float4*)(lstmK + (size_t)LLd * U4); // rows 256..511

    for (int t = 0; t < TT; ++t) {
        // ---------- phase A: combined q|rec matvec (blocks 64..147) ----------
        if (bid >= 64) {
            const int j = bid - 64;
            wait_flags(g_fh, 148, t);
            {
                const float4* hbuf = (const float4*)(g_hT + ((t+1)&1)*HN);
                for (int i = tid; i < 4096; i += NTHR)
                    ((float4*)hT)[i] = __ldcg(hbuf + i);
            }
            __syncthreads();
#pragma unroll 1
            for (int pass = 0; pass < 2; ++pass) {
                const int u = (pass == 0) ? j : ((j < 76) ? 84 + j : -1);
                if (u < 0) break;
                const int c0 = u * 16;
                {
                    const int b = tid & 31, cq = (tid >> 5) & 3, ks = tid >> 7;
                    const float4* wp = Rq4 + (size_t)(ks * 64) * 640 + (c0 >> 2) + cq;
                    const float* hp = hT + (ks * 64) * 32 + b;
                    float4 acc = make_float4(0.f,0.f,0.f,0.f);
#pragma unroll 8
                    for (int k = 0; k < 64; ++k) {
                        float hv = hp[k * 32];
                        float4 w = __ldg(wp); wp += 640;
                        acc.x += hv*w.x; acc.y += hv*w.y; acc.z += hv*w.z; acc.w += hv*w.w;
                    }
                    float* pd = pA + ks*512 + (cq*4)*32 + b;
                    pd[0] = acc.x; pd[32] = acc.y; pd[64] = acc.z; pd[96] = acc.w;
                }
                __syncthreads();
                if (tid < 512) {
                    const int c = tid >> 5, b = tid & 31;
                    float s = 0.f;
#pragma unroll
                    for (int jj = 0; jj < 8; ++jj) s += pA[jj*512 + c*32 + b];
                    const int col = c0 + c;
                    if (col < UU) {
                        s += __ldg(qb + col);
                        g_q[b*UU + col] = s;
                    } else {
                        const int rc = col - UU;
                        s += __ldcg(&g_xpart[((size_t)t*BB + b)*U4 + rc]);
                        g_rec[rc*32 + b] = s;
                    }
                }
                arrive((u < 32) ? &g_fq[u*32] : &g_frec[(u-32)*32], t + 1);
            }
        }

        // ---------- phase B: attention (blocks 0..63) ----------
        if (bid < 64) {
            const int b = bid >> 1, half = bid & 1, m0h = half * 100;
            wait_flags(g_fq, 32, t + 1);
            if (tid < UU) { q_s[tid] = __ldcg(&g_q[b*UU + tid]); v_s[tid] = __ldg(vW + tid); }
            __syncthreads();
            for (int m = wid; m < 100; m += 32) {
                const float* krow = g_keys + ((size_t)(b*MMa + m0h + m)) * UU;
                float acc = 0.f;
#pragma unroll
                for (int jj = 0; jj < 16; ++jj) {
                    int uu = lane + 32*jj;
                    acc += v_s[uu] * tanh_ap(__ldg(krow + uu) + q_s[uu]);
                }
#pragma unroll
                for (int o = 16; o > 0; o >>= 1) acc += __shfl_down_sync(0xffffffffu, acc, o);
                if (lane == 0) sc[m] = acc + vb0;
            }
            __syncthreads();
            if (tid < 32) {
                float v[4];
#pragma unroll
                for (int jj = 0; jj < 4; ++jj) {
                    int m = tid + 32*jj;
                    v[jj] = (m < 100) ? sc[m] : -1e30f;
                }
                float mx = fmaxf(fmaxf(v[0], v[1]), fmaxf(v[2], v[3]));
#pragma unroll
                for (int o = 16; o > 0; o >>= 1) mx = fmaxf(mx, __shfl_xor_sync(0xffffffffu, mx, o));
                float ssum = 0.f;
#pragma unroll
                for (int jj = 0; jj < 4; ++jj) {
                    int m = tid + 32*jj;
                    float e = (m < 100) ? __expf(v[jj] - mx) : 0.f;
                    if (m < 128) sc[m] = e;
                    ssum += e;
                }
#pragma unroll
                for (int o = 16; o > 0; o >>= 1) ssum += __shfl_xor_sync(0xffffffffu, ssum, o);
                if (tid == 0) { g_stats[b*4 + half*2] = mx; g_stats[b*4 + half*2 + 1] = ssum; }
            }
            __syncthreads();
            {
                const int d = tid & 255, mp = tid >> 8;
                const float* att = attended + ((size_t)(b*MMa + m0h + mp*25)) * LLd + d;
                float acc = 0.f;
#pragma unroll
                for (int m = 0; m < 25; ++m) acc += sc[mp*25 + m] * __ldg(att + (size_t)m * LLd);
                ctxp[mp*256 + d] = acc;
            }
            __syncthreads();
            if (tid < 256)
                g_actxT[half*8192 + tid*32 + b] =
                    ctxp[tid] + ctxp[256+tid] + ctxp[512+tid] + ctxp[768+tid];
            arrive(&g_fctx[bid*32], t + 1);
        }

        // ---------- phase C: gates (blocks 0..127) ----------
        if (bid < 128) {
            const int u0 = bid * 4;
            wait_flags(g_fctx, 64, t + 1);
            if (tid < 32) {
                float m1 = __ldcg(&g_stats[tid*4 + 0]), s1 = __ldcg(&g_stats[tid*4 + 1]);
                float m2 = __ldcg(&g_stats[tid*4 + 2]), s2 = __ldcg(&g_stats[tid*4 + 3]);
                float mxa = fmaxf(m1, m2);
                float w1 = __expf(m1 - mxa), w2 = __expf(m2 - mxa);
                float inv = 1.f / (w1*s1 + w2*s2);
                a1s[tid] = w1 * inv; a2s[tid] = w2 * inv;
            }
            __syncthreads();
            for (int i = tid; i < 8192; i += NTHR) {
                int b2 = i & 31;
                ctxT[i] = a1s[b2]*__ldcg(&g_actxT[i]) + a2s[b2]*__ldcg(&g_actxT[8192 + i]);
            }
            wait_flags(g_frec, 128, t + 1);   // includes __syncthreads (covers ctxT)
            {
                const int b2 = tid & 31, g = (tid >> 5) & 3, ks = tid >> 7;
                const float4* wp = K24 + (size_t)(ks*32)*512 + ((g*UU + u0) >> 2);
                const float* cp = ctxT + (ks*32)*32 + b2;
                float4 acc = make_float4(0.f,0.f,0.f,0.f);
#pragma unroll 8
                for (int k = 0; k < 32; ++k) {
                    float cv = cp[k*32];
                    float4 w = __ldg(wp); wp += 512;
                    acc.x += cv*w.x; acc.y += cv*w.y; acc.z += cv*w.z; acc.w += cv*w.w;
                }
                float* pd = pC + ks*512 + (g*4)*32 + b2;
                pd[0] = acc.x; pd[32] = acc.y; pd[64] = acc.z; pd[96] = acc.w;
            }
            __syncthreads();
            if (tid < 512) {
                const int c16 = tid >> 5, b2 = tid & 31;   // c16 = g*4 + j
                float s = 0.f;
#pragma unroll
                for (int jj = 0; jj < 8; ++jj) s += pC[jj*512 + c16*32 + b2];
                const int g = c16 >> 2, cc = c16 & 3;
                s += __ldcg(&g_rec[(g*UU + u0 + cc)*32 + b2]);
                zsm[c16*32 + b2] = s;
            }
            __syncthreads();
            if (tid < 128) {
                const int uu = tid >> 5, b2 = tid & 31;
                float ig = sig(zsm[(0  + uu)*32 + b2]);
                float fg = sig(zsm[(4  + uu)*32 + b2]);
                float gg = tanhf(zsm[(8  + uu)*32 + b2]);
                float og = sig(zsm[(12 + uu)*32 + b2]);
                float cn = fg * creg + ig * gg;
                creg = cn;
                float hn = og * tanhf(cn);
                g_hT[(t&1)*HN + (u0 + uu)*32 + b2] = hn;
                g_x[((size_t)t*BB + b2)*UU + u0 + uu] = hn;
            }
        }
        arrive(&g_fh[bid*32], t + 1);
    }
}

// ============================================================
// persistent GRU: 128 blocks × 4 cells, double-buffered h, 1 gate/step
// ============================================================
#define SMF_G 19840
__global__ void __launch_bounds__(NTHR, 1) gru_seq(
    const float* __restrict__ R, const float* __restrict__ br,
    const float* __restrict__ xz, float* __restrict__ yout, int accumulate)
{
    extern __shared__ float sm[];
    float* hT  = sm;                 // [512][32]
    float* pG  = sm + 16384;         // [8][12][32]
    float* rrs = sm + 16384 + 3072;  // [384]
    const int tid = threadIdx.x, bid = blockIdx.x;
    const int u0 = bid * 4;

    if (tid == 0) g_fgru[bid*32] = 0;
    for (int i = bid*NTHR + tid; i < 2*HN; i += GBLK*NTHR) g_hT[i] = 0.f;
    grid_barrier0(GBLK);

    const float4* R4 = (const float4*)R;   // [512][384 f4]

    for (int t = 0; t < TT; ++t) {
        wait_flags(g_fgru, GBLK, t);
        {
            const float4* hbuf = (const float4*)(g_hT + ((t+1)&1)*HN);
            for (int i = tid; i < 4096; i += NTHR)
                ((float4*)hT)[i] = __ldcg(hbuf + i);
        }
        __syncthreads();

        if (tid < 768) {
            const int b = tid & 31, rest = tid >> 5;     // 24 = 3g x 8ks
            const int g = rest >> 3, ks = rest & 7;
            const float4* wp = R4 + (size_t)(ks*64)*384 + ((g*UU + u0) >> 2);
            const float* hp = hT + (ks*64)*32 + b;
            float4 acc = make_float4(0.f,0.f,0.f,0.f);
#pragma unroll 8
            for (int k = 0; k < 64; ++k) {
                float hv = hp[k*32];
                float4 w = __ldg(wp); wp += 384;
                acc.x += hv*w.x; acc.y += hv*w.y; acc.z += hv*w.z; acc.w += hv*w.w;
            }
            float* pd = pG + ks*384 + (g*4)*32 + b;
            pd[0] = acc.x; pd[32] = acc.y; pd[64] = acc.z; pd[96] = acc.w;
        }
        __syncthreads();
        if (tid < 384) {
            const int g = tid >> 7, uu = (tid >> 5) & 3, b = tid & 31;
            float s = 0.f;
#pragma unroll
            for (int jj = 0; jj < 8; ++jj) s += pG[jj*384 + (g*4 + uu)*32 + b];
            rrs[tid] = s + __ldg(br + g*UU + u0 + uu);
        }
        __syncthreads();
        if (tid < 128) {
            const int uu = tid >> 5, b = tid & 31;
            const int ug = u0 + uu;
            const float* xzr = xz + ((size_t)t*BB + b) * U3;
            float z = sig(__ldg(xzr + ug)           + rrs[uu*32 + b]);
            float r = sig(__ldg(xzr + UU + ug)      + rrs[128 + uu*32 + b]);
            float hh = tanhf(__ldg(xzr + 2*UU + ug) + r * rrs[256 + uu*32 + b]);
            float hold = hT[ug*32 + b];
            float hn = z * hold + (1.f - z) * hh;
            g_hT[(t&1)*HN + ug*32 + b] = hn;
            size_t oi = ((size_t)t*BB + b)*UU + ug;
            if (accumulate) yout[oi] += hn; else yout[oi] = hn;
        }
        arrive(&g_fgru[bid*32], t + 1);
    }
}

// ---------------- launch ----------------
extern "C" void kernel_launch(void* const* d_in, const int* in_sizes, int n_in,
                              void* d_out, int out_size)
{
    const float* inputs   = (const float*)d_in[0];
    const float* attended = (const float*)d_in[1];
    const float* pre_W1   = (const float*)d_in[2];
    const float* pre_b1   = (const float*)d_in[3];
    const float* pre_W2   = (const float*)d_in[4];
    const float* pre_b2   = (const float*)d_in[5];
    const float* key_W    = (const float*)d_in[6];
    const float* key_b    = (const float*)d_in[7];
    const float* query_W  = (const float*)d_in[8];
    const float* query_b  = (const float*)d_in[9];
    const float* attnv_W  = (const float*)d_in[10];
    const float* attnv_b  = (const float*)d_in[11];
    const float* lstm_K   = (const float*)d_in[12];
    const float* lstm_R   = (const float*)d_in[13];
    const float* lstm_b   = (const float*)d_in[14];
    const float* gru1_K   = (const float*)d_in[15];
    const float* gru1_R   = (const float*)d_in[16];
    const float* gru1_b   = (const float*)d_in[17];
    const float* gru2_K   = (const float*)d_in[18];
    const float* gru2_R   = (const float*)d_in[19];
    const float* gru2_b   = (const float*)d_in[20];
    const float* proj_W   = (const float*)d_in[21];
    float* out = (float*)d_out;

    float *inT, *h1, *xp, *keys, *xpart, *x, *y1, *xsum, *xz;
    cudaGetSymbolAddress((void**)&inT,   g_inT);
    cudaGetSymbolAddress((void**)&h1,    g_h1);
    cudaGetSymbolAddress((void**)&xp,    g_xp);
    cudaGetSymbolAddress((void**)&keys,  g_keys);
    cudaGetSymbolAddress((void**)&xpart, g_xpart);
    cudaGetSymbolAddress((void**)&x,     g_x);
    cudaGetSymbolAddress((void**)&y1,    g_y1);
    cudaGetSymbolAddress((void**)&xsum,  g_xsum);
    cudaGetSymbolAddress((void**)&xz,    g_xz);

    cudaFuncSetAttribute(lstm_attn, cudaFuncAttributeMaxDynamicSharedMemorySize,
                         SMF_L * (int)sizeof(float));
    cudaFuncSetAttribute(gru_seq, cudaFuncAttributeMaxDynamicSharedMemorySize,
                         SMF_G * (int)sizeof(float));

    // 1) repack + combined weights
    repack_inputs<<<(BT*MELD + 255)/256, 256>>>(inputs);
    build_Rq<<<(UU*CW + 255)/256, 256>>>(query_W, lstm_R);
    // 2) prenet
    gemm128<<<dim3(4, 100), 256>>>(inT, pre_W1, pre_b1, h1, UU,  MELD, 1, 0);
    gemm128<<<dim3(2, 100), 256>>>(h1,  pre_W2, pre_b2, xp, LLd, UU,   1, 0);
    // 3) keys
    gemm128<<<dim3(4, 50),  256>>>(attended, key_W, key_b, keys, UU, LLd, 0, 0);
    // 4) LSTM input part: xp @ lstm_K[:256] + lstm_b
    gemm128<<<dim3(16, 100), 256>>>(xp, lstm_K, lstm_b, xpart, U4, LLd, 0, 0);
    // 5) attention LSTM (persistent)
    lstm_attn<<<NBLK, NTHR, SMF_L*sizeof(float)>>>(
        attended, query_b, attnv_W, attnv_b, lstm_K);
    // 6) GRU1
    gemm128<<<dim3(12, 100), 256>>>(x, gru1_K, gru1_b, xz, U3, UU, 0, 0);
    gru_seq<<<GBLK, NTHR, SMF_G*sizeof(float)>>>(gru1_R, gru1_b + U3, xz, y1, 0);
    // 7) xsum = x + y1
    add_kernel<<<(BT*UU + 255)/256, 256>>>();
    // 8) GRU2 on xsum, accumulate y2 into xsum
    gemm128<<<dim3(12, 100), 256>>>(xsum, gru2_K, gru2_b, xz, U3, UU, 0, 0);
    gru_seq<<<GBLK, NTHR, SMF_G*sizeof(float)>>>(gru2_R, gru2_b + U3, xz, xsum, 1);
    // 9) mel = relu(xsum @ proj_W) remapped to [B,T,80]
    gemm128<<<dim3(1, 100), 256>>>(xsum, proj_W, nullptr, out, MELD, UU, 1, 1);
}